// round 16
// baseline (speedup 1.0000x reference)
#include <cuda_runtime.h>
#include <cuda_fp16.h>
#include <math.h>
#include <stdint.h>

// Problem constants: B=8, Sq=Skv=2048, DIM=1024, CTX=768
#define BATCH 8
#define SEQ   2048
#define DIM   1024
#define CTX   768
#define MROWS (BATCH * SEQ)   // 16384

// ---------------------------------------------------------------------------
// Device scratch (allocation-free: __device__ globals)  — fp16 operands
// ---------------------------------------------------------------------------
__device__ __half g_xh [(long long)MROWS * DIM];
__device__ __half g_ch [(long long)MROWS * CTX];
__device__ __half g_wqh[(long long)DIM * DIM];
__device__ __half g_wkh[(long long)DIM * CTX];
__device__ __half g_wvh[(long long)DIM * CTX];
__device__ __half g_woh[(long long)DIM * DIM];
__device__ __half g_qh [(long long)MROWS * DIM];
__device__ __half g_kh [(long long)MROWS * DIM];
__device__ __half g_vh [(long long)MROWS * DIM];
__device__ __half g_vth[(long long)MROWS * DIM];   // per-batch [DIM, SEQ]
__device__ __half g_oh [(long long)MROWS * DIM];
__device__ __half g_ph [(long long)BATCH * SEQ * SEQ];
__device__ float  g_s  [(long long)BATCH * SEQ * SEQ];

// ---------------------------------------------------------------------------
// PTX helpers (sm_80-era: compile clean at compute_103)
// ---------------------------------------------------------------------------
__device__ __forceinline__ uint32_t smem_u32(const void* p) {
    uint32_t a;
    asm("{ .reg .u64 t; cvta.to.shared.u64 t, %1; cvt.u32.u64 %0, t; }" : "=r"(a) : "l"(p));
    return a;
}
__device__ __forceinline__ void cpasync16(uint32_t saddr, const void* g) {
    asm volatile("cp.async.cg.shared.global [%0], [%1], 16;" :: "r"(saddr), "l"(g));
}
#define CP_COMMIT() asm volatile("cp.async.commit_group;" ::: "memory")
#define CP_WAIT(n)  asm volatile("cp.async.wait_group %0;" :: "n"(n) : "memory")

__device__ __forceinline__ void ldsm_x4(uint32_t* r, uint32_t addr) {
    asm volatile("ldmatrix.sync.aligned.m8n8.x4.shared.b16 {%0,%1,%2,%3}, [%4];"
        : "=r"(r[0]), "=r"(r[1]), "=r"(r[2]), "=r"(r[3]) : "r"(addr));
}
__device__ __forceinline__ void mma16816(float* d, const uint32_t* a, const uint32_t* b) {
    asm volatile("mma.sync.aligned.m16n8k16.row.col.f32.f16.f16.f32 "
        "{%0,%1,%2,%3}, {%4,%5,%6,%7}, {%8,%9}, {%0,%1,%2,%3};"
        : "+f"(d[0]), "+f"(d[1]), "+f"(d[2]), "+f"(d[3])
        : "r"(a[0]), "r"(a[1]), "r"(a[2]), "r"(a[3]), "r"(b[0]), "r"(b[1]));
}

union U8 { uint4 v; __half h[8]; };

// swizzle select for 64B rows (conflict-free ldmatrix + cp.async; proven R8-R14)
__device__ __forceinline__ uint32_t swz(uint32_t r) {
    return (((r >> 1) & 1u) << 1) | ((r >> 2) & 1u);
}

// ---------------------------------------------------------------------------
// Convert fp32 -> fp16  (n divisible by 2048)
// ---------------------------------------------------------------------------
__global__ void __launch_bounds__(256)
conv_f32(const float* __restrict__ in, __half* __restrict__ hi)
{
    long long i = ((long long)blockIdx.x * 256 + threadIdx.x) * 8;
    float4 a = *(const float4*)(in + i);
    float4 b = *(const float4*)(in + i + 4);
    float v[8] = {a.x, a.y, a.z, a.w, b.x, b.y, b.z, b.w};
    U8 u;
#pragma unroll
    for (int e = 0; e < 8; ++e) u.h[e] = __float2half_rn(v[e]);
    *(uint4*)(hi + i) = u.v;
}

// ---------------------------------------------------------------------------
// Transpose V: [16384,1024] -> per-batch [1024,2048]
// ---------------------------------------------------------------------------
__global__ void __launch_bounds__(256)
transpose_v(const __half* __restrict__ in, __half* __restrict__ out)
{
    __shared__ __half s[64][80];
    const int tBase = blockIdx.y * 64;          // global token row
    const int dBase = blockIdx.x * 64;          // dim
    const int b  = tBase >> 11;
    const int t0 = tBase & 2047;
    const int tid = threadIdx.x;
#pragma unroll
    for (int p = 0; p < 2; ++p) {
        int task = tid + p * 256;
        int r = task >> 3, cg = task & 7;
        uint4 v = *(const uint4*)(in + (long long)(tBase + r) * DIM + dBase + cg * 8);
        *(uint4*)&s[r][cg * 8] = v;
    }
    __syncthreads();
#pragma unroll
    for (int p = 0; p < 2; ++p) {
        int task = tid + p * 256;
        int d = task >> 3, tg = task & 7;
        U8 u;
#pragma unroll
        for (int e = 0; e < 8; ++e) u.h[e] = s[tg * 8 + e][d];
        *(uint4*)(out + (long long)b * (DIM * SEQ) + (long long)(dBase + d) * SEQ + t0 + tg * 8) = u.v;
    }
}

// ---------------------------------------------------------------------------
// Row softmax over 2048 cols -> fp16 output
// ---------------------------------------------------------------------------
__global__ void __launch_bounds__(256)
softmax_half(const float* __restrict__ S, __half* __restrict__ Ph, float scale)
{
    const long long row = blockIdx.x;
    const float* p = S + row * (long long)SEQ;
    const int tid = threadIdx.x, lane = tid & 31, wid = tid >> 5;
    __shared__ float buf[8];

    float x[8];
#pragma unroll
    for (int i = 0; i < 8; ++i) x[i] = p[tid + i * 256] * scale;

    float m = x[0];
#pragma unroll
    for (int i = 1; i < 8; ++i) m = fmaxf(m, x[i]);
#pragma unroll
    for (int off = 16; off > 0; off >>= 1)
        m = fmaxf(m, __shfl_xor_sync(0xFFFFFFFFu, m, off));
    if (lane == 0) buf[wid] = m;
    __syncthreads();
    float mfull = buf[0];
#pragma unroll
    for (int w = 1; w < 8; ++w) mfull = fmaxf(mfull, buf[w]);
    __syncthreads();

    float e[8], sum = 0.0f;
#pragma unroll
    for (int i = 0; i < 8; ++i) { e[i] = __expf(x[i] - mfull); sum += e[i]; }
#pragma unroll
    for (int off = 16; off > 0; off >>= 1)
        sum += __shfl_xor_sync(0xFFFFFFFFu, sum, off);
    if (lane == 0) buf[wid] = sum;
    __syncthreads();
    float sfull = 0.0f;
#pragma unroll
    for (int w = 0; w < 8; ++w) sfull += buf[w];
    const float inv = 1.0f / sfull;

    __half* ph = Ph + row * (long long)SEQ;
#pragma unroll
    for (int i = 0; i < 8; ++i)
        ph[tid + i * 256] = __float2half_rn(e[i] * inv);
}

// ---------------------------------------------------------------------------
// fp16 TN GEMM body:  D[M,N] = A[M,K] * B[N,K]^T (+bias)
// Tile 128x128, BK=32, 4 warps (2x2 -> warp tile 64x64), 128 threads.
// PAIRED-STAGE pipeline, 6 smem buffers (3 pairs x 2 stages of 16KB each).
// WAIT-DEPTH FIX vs R15: boundary uses CP_WAIT(1) (outstanding = {p+1, p+2};
// only p+1 must complete) — R15's CP_WAIT(0) drained the just-issued pair
// p+2 too, collapsing the prefetch distance to zero every pair.
// One CP_WAIT+__syncthreads per PAIR (16 boundaries for K=1024).
// A frags double-buffered per k16 step; B frags double-buffered per chunk
// parity with ldsm spread 1-per-i. 2 CTAs/SM (96KB smem each).
// EPI=0: fp32 C (+bias).  EPI=2: fp16 C (+bias).
// ---------------------------------------------------------------------------
#define MAT_HALF    8192                     // 128 rows * 64 B
#define STAGE_BYTES (2 * MAT_HALF)           // A | B = 16384
#define NSTAGE 6
#define SMEM_TOTAL  (NSTAGE * STAGE_BYTES)   // 98304 -> 2 CTAs/SM
#define A_OFF  0
#define B_OFF  MAT_HALF

template<int EPI>
__device__ __forceinline__ void
gemm_body(const __half* __restrict__ A, const __half* __restrict__ B,
          float* __restrict__ Cf, __half* __restrict__ Ch,
          const float* __restrict__ bias, int K, int N,
          int bm0, int bn0, long long cOff)
{
    extern __shared__ __align__(128) char smem[];
    const uint32_t sbase = smem_u32(smem);

    const int tid  = threadIdx.x;
    const int wid  = tid >> 5;
    const int lane = tid & 31;
    const int wm   = wid >> 1;      // 0..1  -> 64 rows
    const int wn   = wid & 1;       // 0..1  -> 64 cols

    // ---- loader: 128 threads; row = tid/4 (+32,+64,+96), chunk = tid%4
    const int ldRow = tid >> 2;           // 0..31
    const int ldC   = tid & 3;
    const uint32_t ldSw = sbase + (uint32_t)(ldRow * 64 + (((uint32_t)ldC ^ swz(ldRow)) << 4));
    const __half* srcA = A + (long long)(bm0 + ldRow) * K + ldC * 8;
    const __half* srcB = B + (long long)(bn0 + ldRow) * K + ldC * 8;
    const long long rowSkip = (long long)32 * K;

    // ---- ldmatrix row components ----
    const uint32_t aRow   = (uint32_t)(wm * 64 + (lane & 15));            // + i*16
    const uint32_t aSel   = (uint32_t)(lane >> 4);                        // chunk lsb
    const uint32_t bRowX4 = (uint32_t)(wn * 64 + (lane & 7) + (((lane >> 4) & 1) << 3));
    const uint32_t bSel   = (uint32_t)((lane >> 3) & 1);

    float acc[4][8][4];
#pragma unroll
    for (int i = 0; i < 4; ++i)
#pragma unroll
        for (int j = 0; j < 8; ++j)
#pragma unroll
            for (int r = 0; r < 4; ++r) acc[i][j][r] = 0.0f;

    const int nPairs = K >> 6;            // K multiple of 64 always here

    auto load_stage_buf = [&](int bufIdx, int sIdx) {
        const uint32_t sb = ldSw + (uint32_t)bufIdx * STAGE_BYTES;
        const long long g0 = (long long)(sIdx << 5);
#pragma unroll
        for (int rg = 0; rg < 4; ++rg) {
            cpasync16(sb + A_OFF + rg * (32 * 64), srcA + g0 + rg * rowSkip);
            cpasync16(sb + B_OFF + rg * (32 * 64), srcB + g0 + rg * rowSkip);
        }
    };
    auto load_pair = [&](int p, int bp) {
        load_stage_buf(2 * bp,     2 * p);
        load_stage_buf(2 * bp + 1, 2 * p + 1);
        CP_COMMIT();
    };

    // fragment buffers: A double per k16 step, B double per chunk parity
    uint32_t fah[2][4];
    uint32_t fb[2][8][2];

    auto load_A = [&](int buf, uint32_t sb, int kb, int i) {
        const uint32_t r = aRow + (uint32_t)(i * 16);
        const uint32_t c = (uint32_t)(kb * 2) + aSel;
        const uint32_t addr = sb + A_OFF + r * 64 + ((c ^ swz(r)) << 4);
        ldsm_x4(fah[buf], addr);
    };
    auto load_B_part = [&](int par, uint32_t sb, int kb, int jp) {
        const uint32_t r = bRowX4 + (uint32_t)(jp * 16);
        const uint32_t c = (uint32_t)(kb * 2) + bSel;
        const uint32_t addr = sb + B_OFF + r * 64 + ((c ^ swz(r)) << 4);
        uint32_t t[4];
        ldsm_x4(t, addr);
        fb[par][jp * 2][0] = t[0];      fb[par][jp * 2][1] = t[1];
        fb[par][jp * 2 + 1][0] = t[2];  fb[par][jp * 2 + 1][1] = t[3];
    };

// one k16 chunk: compute fb[PAR]; prefetch fb[PAR^1] <- (SBP, KBP); A chain
#define HALF_STEP(SBC, KBC, PAR, SBP, KBP, DOPRE)                              \
    _Pragma("unroll")                                                          \
    for (int i = 0; i < 4; ++i) {                                              \
        const int cur = i & 1, nxt = cur ^ 1;                                  \
        if (i < 3)        load_A(nxt, (SBC), (KBC), i + 1);                    \
        else if (DOPRE)   load_A(nxt, (SBP), (KBP), 0);                        \
        if (DOPRE)        load_B_part((PAR) ^ 1, (SBP), (KBP), i);             \
        _Pragma("unroll")                                                      \
        for (int j = 0; j < 8; ++j)                                            \
            mma16816(acc[i][j], fah[cur], fb[(PAR)][j]);                       \
    }

    // ---- prologue: pairs 0 and 1 in flight; wait pair 0 only, sync, preload
    load_pair(0, 0);
    load_pair(1, 1);
    CP_WAIT(1);                 // pair 0 complete, pair 1 still in flight
    __syncthreads();
#pragma unroll
    for (int jp = 0; jp < 4; ++jp) load_B_part(0, sbase, 0, jp);
    load_A(0, sbase, 0, 0);

    int bp = 0;     // p % 3
    for (int p = 0; p < nPairs; ++p) {
        const int bpn = (bp == 2) ? 0 : bp + 1;       // (p+1) % 3
        const int bpl = (bpn == 2) ? 0 : bpn + 1;     // (p+2) % 3
        // issue next-next pair into pair p-1's buffers (safe after barrier)
        const bool issued = (p + 2 < nPairs);
        if (issued) load_pair(p + 2, bpl);

        const uint32_t sb0  = sbase + (uint32_t)(2 * bp)  * STAGE_BYTES;
        const uint32_t sb1  = sb0 + STAGE_BYTES;
        const uint32_t sbn0 = sbase + (uint32_t)(2 * bpn) * STAGE_BYTES;
        const bool hasNext = (p + 1 < nPairs);

        HALF_STEP(sb0, 0, 0, sb0, 1, true)
        HALF_STEP(sb0, 1, 1, sb1, 0, true)
        HALF_STEP(sb1, 0, 0, sb1, 1, true)
        HALF_STEP(sb1, 1, 1, sbn0, 0, hasNext)

        if (hasNext) {
            // outstanding groups: {p+1} or {p+1, p+2}. Need only p+1 done.
            if (issued) { CP_WAIT(1); }
            else        { CP_WAIT(0); }
            __syncthreads();
        }
        bp = bpn;
    }
#undef HALF_STEP

    // ---- epilogue ----
    const int r0base = bm0 + wm * 64 + (lane >> 2);
    const int c0base = bn0 + wn * 64 + (lane & 3) * 2;

    float bz[8][2];
#pragma unroll
    for (int j = 0; j < 8; ++j) {
        const int c = c0base + j * 8;
        bz[j][0] = bias ? __ldg(bias + c)     : 0.0f;
        bz[j][1] = bias ? __ldg(bias + c + 1) : 0.0f;
    }

#pragma unroll
    for (int i = 0; i < 4; ++i) {
        const long long r0 = r0base + i * 16;
        const long long r1 = r0 + 8;
#pragma unroll
        for (int j = 0; j < 8; ++j) {
            const int c = c0base + j * 8;
            float v00 = acc[i][j][0] + bz[j][0];
            float v01 = acc[i][j][1] + bz[j][1];
            float v10 = acc[i][j][2] + bz[j][0];
            float v11 = acc[i][j][3] + bz[j][1];
            if (EPI == 0) {
                *(float2*)(Cf + cOff + r0 * N + c) = make_float2(v00, v01);
                *(float2*)(Cf + cOff + r1 * N + c) = make_float2(v10, v11);
            } else {
                *(__half2*)(Ch + cOff + r0 * N + c) =
                    __half2(__float2half_rn(v00), __float2half_rn(v01));
                *(__half2*)(Ch + cOff + r1 * N + c) =
                    __half2(__float2half_rn(v10), __float2half_rn(v11));
            }
        }
    }
}

template<int EPI>
__global__ void __launch_bounds__(128, 2)
gemm_mma(const __half* __restrict__ A, const __half* __restrict__ B,
         float* __restrict__ Cf, __half* __restrict__ Ch,
         const float* __restrict__ bias,
         int K, int N, long long sA, long long sB, long long sC)
{
    gemm_body<EPI>(A + blockIdx.z * sA, B + blockIdx.z * sB, Cf, Ch, bias,
                   K, N, blockIdx.y * 128, blockIdx.x * 128, blockIdx.z * sC);
}

// merged K+V projections: z=0 -> K, z=1 -> V (same A, K=CTX, N=DIM)
__global__ void __launch_bounds__(128, 2)
gemm_kv(const __half* __restrict__ Ac,
        const __half* __restrict__ Bk, const __half* __restrict__ Bv,
        __half* __restrict__ Ck, __half* __restrict__ Cv,
        const float* __restrict__ bk, const float* __restrict__ bv)
{
    const int z = blockIdx.z;
    gemm_body<2>(Ac, z ? Bv : Bk, nullptr, z ? Cv : Ck, z ? bv : bk,
                 CTX, DIM, blockIdx.y * 128, blockIdx.x * 128, 0);
}

// ---------------------------------------------------------------------------
// kernel_launch — gemmQ at launch index 3 (ncu profiles that slot).
// ---------------------------------------------------------------------------
extern "C" void kernel_launch(void* const* d_in, const int* in_sizes, int n_in,
                              void* d_out, int out_size)
{
    const float* x   = (const float*)d_in[0];
    const float* ctx = (const float*)d_in[1];
    const float* Wq  = (const float*)d_in[2];
    const float* bq  = (const float*)d_in[3];
    const float* Wk  = (const float*)d_in[4];
    const float* bk  = (const float*)d_in[5];
    const float* Wv  = (const float*)d_in[6];
    const float* bv  = (const float*)d_in[7];
    const float* Wo  = (const float*)d_in[8];
    const float* bo  = (const float*)d_in[9];
    float* out = (float*)d_out;

    __half *xh, *ch, *wqh, *wkh, *wvh, *woh;
    __half *qh, *kh, *vh, *vth, *oh, *ph;
    float* S;
    cudaGetSymbolAddress((void**)&xh, g_xh);
    cudaGetSymbolAddress((void**)&ch, g_ch);
    cudaGetSymbolAddress((void**)&wqh, g_wqh);
    cudaGetSymbolAddress((void**)&wkh, g_wkh);
    cudaGetSymbolAddress((void**)&wvh, g_wvh);
    cudaGetSymbolAddress((void**)&woh, g_woh);
    cudaGetSymbolAddress((void**)&qh, g_qh);
    cudaGetSymbolAddress((void**)&kh, g_kh);
    cudaGetSymbolAddress((void**)&vh, g_vh);
    cudaGetSymbolAddress((void**)&vth, g_vth);
    cudaGetSymbolAddress((void**)&oh, g_oh);
    cudaGetSymbolAddress((void**)&ph, g_ph);
    cudaGetSymbolAddress((void**)&S, g_s);

    cudaFuncSetAttribute(gemm_mma<0>, cudaFuncAttributeMaxDynamicSharedMemorySize, SMEM_TOTAL);
    cudaFuncSetAttribute(gemm_mma<2>, cudaFuncAttributeMaxDynamicSharedMemorySize, SMEM_TOTAL);
    cudaFuncSetAttribute(gemm_kv,     cudaFuncAttributeMaxDynamicSharedMemorySize, SMEM_TOTAL);

    dim3 grdP(DIM / 128, MROWS / 128, 1);
    dim3 blk(128);

    // idx 0-2: conversions feeding gemmQ
    conv_f32<<<(MROWS * (long long)DIM) / 2048, 256>>>(x, xh);
    conv_f32<<<(MROWS * (long long)CTX) / 2048, 256>>>(ctx, ch);
    conv_f32<<<(DIM * (long long)DIM) / 2048, 256>>>(Wq, wqh);
    // idx 3: Q projection  <-- ncu profiles this launch
    gemm_mma<2><<<grdP, blk, SMEM_TOTAL>>>(xh, wqh, nullptr, qh, bq,
                                           DIM, DIM, 0, 0, 0);
    // remaining conversions
    conv_f32<<<(DIM * (long long)CTX) / 2048, 256>>>(Wk, wkh);
    conv_f32<<<(DIM * (long long)CTX) / 2048, 256>>>(Wv, wvh);
    conv_f32<<<(DIM * (long long)DIM) / 2048, 256>>>(Wo, woh);
    // merged K + V projections (2048 CTAs -> ~99% wave efficiency)
    {
        dim3 grdKV(DIM / 128, MROWS / 128, 2);
        gemm_kv<<<grdKV, blk, SMEM_TOTAL>>>(ch, wkh, wvh, kh, vh, bk, bv);
    }

    // transpose V per batch -> [DIM, SEQ]
    transpose_v<<<dim3(DIM / 64, MROWS / 64, 1), 256>>>(vh, vth);

    // scores S = Q K^T (fp32)
    {
        dim3 grd(SEQ / 128, SEQ / 128, BATCH);
        gemm_mma<0><<<grd, blk, SMEM_TOTAL>>>(qh, kh, S, nullptr, nullptr,
                                              DIM, SEQ,
                                              (long long)SEQ * DIM, (long long)SEQ * DIM,
                                              (long long)SEQ * SEQ);
    }

    // softmax -> P (fp16)
    softmax_half<<<BATCH * SEQ, 256>>>(S, ph, 1.0f / sqrtf((float)DIM));

    // O = P V  -> fp16
    {
        dim3 grd(DIM / 128, SEQ / 128, BATCH);
        gemm_mma<2><<<grd, blk, SMEM_TOTAL>>>(ph, vth, nullptr, oh, nullptr,
                                              SEQ, DIM,
                                              (long long)SEQ * SEQ, (long long)DIM * SEQ,
                                              (long long)SEQ * DIM);
    }

    // out = O Wo^T + bo (fp32 -> d_out)
    gemm_mma<0><<<grdP, blk, SMEM_TOTAL>>>(oh, woh, out, nullptr, bo,
                                           DIM, DIM, 0, 0, 0);
}

// round 17
// speedup vs baseline: 1.0395x; 1.0395x over previous
#include <cuda_runtime.h>
#include <cuda_fp16.h>
#include <math.h>
#include <stdint.h>

// Problem constants: B=8, Sq=Skv=2048, DIM=1024, CTX=768
#define BATCH 8
#define SEQ   2048
#define DIM   1024
#define CTX   768
#define MROWS (BATCH * SEQ)   // 16384

// ---------------------------------------------------------------------------
// Device scratch (allocation-free: __device__ globals)  — fp16 operands
// ---------------------------------------------------------------------------
__device__ __half g_xh [(long long)MROWS * DIM];
__device__ __half g_ch [(long long)MROWS * CTX];
__device__ __half g_wqh[(long long)DIM * DIM];
__device__ __half g_wkh[(long long)DIM * CTX];
__device__ __half g_wvh[(long long)DIM * CTX];
__device__ __half g_woh[(long long)DIM * DIM];
__device__ __half g_qh [(long long)MROWS * DIM];
__device__ __half g_kh [(long long)MROWS * DIM];
__device__ __half g_vh [(long long)MROWS * DIM];
__device__ __half g_vth[(long long)MROWS * DIM];   // per-batch [DIM, SEQ]
__device__ __half g_oh [(long long)MROWS * DIM];
__device__ __half g_ph [(long long)BATCH * SEQ * SEQ];
__device__ float  g_s  [(long long)BATCH * SEQ * SEQ];

// ---------------------------------------------------------------------------
// PTX helpers (sm_80-era: compile clean at compute_103)
// ---------------------------------------------------------------------------
__device__ __forceinline__ uint32_t smem_u32(const void* p) {
    uint32_t a;
    asm("{ .reg .u64 t; cvta.to.shared.u64 t, %1; cvt.u32.u64 %0, t; }" : "=r"(a) : "l"(p));
    return a;
}
__device__ __forceinline__ void cpasync16(uint32_t saddr, const void* g) {
    asm volatile("cp.async.cg.shared.global [%0], [%1], 16;" :: "r"(saddr), "l"(g));
}
#define CP_COMMIT() asm volatile("cp.async.commit_group;" ::: "memory")
#define CP_WAIT(n)  asm volatile("cp.async.wait_group %0;" :: "n"(n) : "memory")

__device__ __forceinline__ void ldsm_x4(uint32_t* r, uint32_t addr) {
    asm volatile("ldmatrix.sync.aligned.m8n8.x4.shared.b16 {%0,%1,%2,%3}, [%4];"
        : "=r"(r[0]), "=r"(r[1]), "=r"(r[2]), "=r"(r[3]) : "r"(addr));
}
__device__ __forceinline__ void mma16816(float* d, const uint32_t* a, const uint32_t* b) {
    asm volatile("mma.sync.aligned.m16n8k16.row.col.f32.f16.f16.f32 "
        "{%0,%1,%2,%3}, {%4,%5,%6,%7}, {%8,%9}, {%0,%1,%2,%3};"
        : "+f"(d[0]), "+f"(d[1]), "+f"(d[2]), "+f"(d[3])
        : "r"(a[0]), "r"(a[1]), "r"(a[2]), "r"(a[3]), "r"(b[0]), "r"(b[1]));
}

union U8 { uint4 v; __half h[8]; };

// swizzle select for 64B rows (conflict-free ldmatrix + cp.async; proven R8-R14)
__device__ __forceinline__ uint32_t swz(uint32_t r) {
    return (((r >> 1) & 1u) << 1) | ((r >> 2) & 1u);
}

// ---------------------------------------------------------------------------
// Convert fp32 -> fp16  (n divisible by 2048)
// ---------------------------------------------------------------------------
__global__ void __launch_bounds__(256)
conv_f32(const float* __restrict__ in, __half* __restrict__ hi)
{
    long long i = ((long long)blockIdx.x * 256 + threadIdx.x) * 8;
    float4 a = *(const float4*)(in + i);
    float4 b = *(const float4*)(in + i + 4);
    float v[8] = {a.x, a.y, a.z, a.w, b.x, b.y, b.z, b.w};
    U8 u;
#pragma unroll
    for (int e = 0; e < 8; ++e) u.h[e] = __float2half_rn(v[e]);
    *(uint4*)(hi + i) = u.v;
}

// ---------------------------------------------------------------------------
// Transpose V: [16384,1024] -> per-batch [1024,2048]
// ---------------------------------------------------------------------------
__global__ void __launch_bounds__(256)
transpose_v(const __half* __restrict__ in, __half* __restrict__ out)
{
    __shared__ __half s[64][80];
    const int tBase = blockIdx.y * 64;          // global token row
    const int dBase = blockIdx.x * 64;          // dim
    const int b  = tBase >> 11;
    const int t0 = tBase & 2047;
    const int tid = threadIdx.x;
#pragma unroll
    for (int p = 0; p < 2; ++p) {
        int task = tid + p * 256;
        int r = task >> 3, cg = task & 7;
        uint4 v = *(const uint4*)(in + (long long)(tBase + r) * DIM + dBase + cg * 8);
        *(uint4*)&s[r][cg * 8] = v;
    }
    __syncthreads();
#pragma unroll
    for (int p = 0; p < 2; ++p) {
        int task = tid + p * 256;
        int d = task >> 3, tg = task & 7;
        U8 u;
#pragma unroll
        for (int e = 0; e < 8; ++e) u.h[e] = s[tg * 8 + e][d];
        *(uint4*)(out + (long long)b * (DIM * SEQ) + (long long)(dBase + d) * SEQ + t0 + tg * 8) = u.v;
    }
}

// ---------------------------------------------------------------------------
// Row softmax over 2048 cols -> fp16 output
// ---------------------------------------------------------------------------
__global__ void __launch_bounds__(256)
softmax_half(const float* __restrict__ S, __half* __restrict__ Ph, float scale)
{
    const long long row = blockIdx.x;
    const float* p = S + row * (long long)SEQ;
    const int tid = threadIdx.x, lane = tid & 31, wid = tid >> 5;
    __shared__ float buf[8];

    float x[8];
#pragma unroll
    for (int i = 0; i < 8; ++i) x[i] = p[tid + i * 256] * scale;

    float m = x[0];
#pragma unroll
    for (int i = 1; i < 8; ++i) m = fmaxf(m, x[i]);
#pragma unroll
    for (int off = 16; off > 0; off >>= 1)
        m = fmaxf(m, __shfl_xor_sync(0xFFFFFFFFu, m, off));
    if (lane == 0) buf[wid] = m;
    __syncthreads();
    float mfull = buf[0];
#pragma unroll
    for (int w = 1; w < 8; ++w) mfull = fmaxf(mfull, buf[w]);
    __syncthreads();

    float e[8], sum = 0.0f;
#pragma unroll
    for (int i = 0; i < 8; ++i) { e[i] = __expf(x[i] - mfull); sum += e[i]; }
#pragma unroll
    for (int off = 16; off > 0; off >>= 1)
        sum += __shfl_xor_sync(0xFFFFFFFFu, sum, off);
    if (lane == 0) buf[wid] = sum;
    __syncthreads();
    float sfull = 0.0f;
#pragma unroll
    for (int w = 0; w < 8; ++w) sfull += buf[w];
    const float inv = 1.0f / sfull;

    __half* ph = Ph + row * (long long)SEQ;
#pragma unroll
    for (int i = 0; i < 8; ++i)
        ph[tid + i * 256] = __float2half_rn(e[i] * inv);
}

// ---------------------------------------------------------------------------
// fp16 TN GEMM body (R14-proven mainloop):  D[M,N] = A[M,K]*B[N,K]^T (+bias)
// Tile 128x128, BK=32, 4 warps (2x2 -> warp tile 64x64), 128 threads.
// 4-stage cp.async pipeline + cross-stage fragment software pipelining.
// Stage boundary: load_stage(s+3); CP_WAIT(1); __syncthreads()  (barrier
// AFTER the per-thread wait -> cross-thread smem visibility).
// A frags double-buffered per k16 step; B frags double-buffered per kb
// parity with ldsm spread 1-per-i. 2 CTAs/SM (64KB smem each).
// EPI=0: fp32 C (+bias).  EPI=2: fp16 C (+bias).
// ---------------------------------------------------------------------------
#define MAT_HALF    8192                     // 128 rows * 64 B
#define STAGE_BYTES (2 * MAT_HALF)           // A | B = 16384
#define NSTAGE 4
#define SMEM_TOTAL  (NSTAGE * STAGE_BYTES)   // 65536 -> 2 CTAs/SM
#define A_OFF  0
#define B_OFF  MAT_HALF

template<int EPI>
__device__ __forceinline__ void
gemm_body(const __half* __restrict__ A, const __half* __restrict__ B,
          float* __restrict__ Cf, __half* __restrict__ Ch,
          const float* __restrict__ bias, int K, int N,
          int bm0, int bn0, long long cOff)
{
    extern __shared__ __align__(128) char smem[];
    const uint32_t sbase = smem_u32(smem);

    const int tid  = threadIdx.x;
    const int wid  = tid >> 5;
    const int lane = tid & 31;
    const int wm   = wid >> 1;      // 0..1  -> 64 rows
    const int wn   = wid & 1;       // 0..1  -> 64 cols

    // ---- loader: 128 threads; row = tid/4 (+32,+64,+96), chunk = tid%4
    const int ldRow = tid >> 2;           // 0..31
    const int ldC   = tid & 3;
    const uint32_t ldSw = sbase + (uint32_t)(ldRow * 64 + (((uint32_t)ldC ^ swz(ldRow)) << 4));
    const __half* srcA = A + (long long)(bm0 + ldRow) * K + ldC * 8;
    const __half* srcB = B + (long long)(bn0 + ldRow) * K + ldC * 8;
    const long long rowSkip = (long long)32 * K;

    // ---- ldmatrix row components ----
    const uint32_t aRow   = (uint32_t)(wm * 64 + (lane & 15));            // + i*16
    const uint32_t aSel   = (uint32_t)(lane >> 4);                        // chunk lsb
    const uint32_t bRowX4 = (uint32_t)(wn * 64 + (lane & 7) + (((lane >> 4) & 1) << 3));
    const uint32_t bSel   = (uint32_t)((lane >> 3) & 1);

    float acc[4][8][4];
#pragma unroll
    for (int i = 0; i < 4; ++i)
#pragma unroll
        for (int j = 0; j < 8; ++j)
#pragma unroll
            for (int r = 0; r < 4; ++r) acc[i][j][r] = 0.0f;

    const int nStages = K >> 5;

    auto load_stage = [&](int s) {
        const uint32_t sb = ldSw + (uint32_t)(s & (NSTAGE - 1)) * STAGE_BYTES;
        const long long g0 = (long long)(s << 5);
#pragma unroll
        for (int rg = 0; rg < 4; ++rg) {
            cpasync16(sb + A_OFF + rg * (32 * 64), srcA + g0 + rg * rowSkip);
            cpasync16(sb + B_OFF + rg * (32 * 64), srcB + g0 + rg * rowSkip);
        }
        CP_COMMIT();
    };

    // fragment buffers: A double per k16 step, B double per kb parity
    uint32_t fah[2][4];
    uint32_t fb[2][8][2];

    auto load_A = [&](int buf, uint32_t sb, int kb, int i) {
        const uint32_t r = aRow + (uint32_t)(i * 16);
        const uint32_t c = (uint32_t)(kb * 2) + aSel;
        const uint32_t addr = sb + A_OFF + r * 64 + ((c ^ swz(r)) << 4);
        ldsm_x4(fah[buf], addr);
    };
    auto load_B_part = [&](int par, uint32_t sb, int kb, int jp) {
        const uint32_t r = bRowX4 + (uint32_t)(jp * 16);
        const uint32_t c = (uint32_t)(kb * 2) + bSel;
        const uint32_t addr = sb + B_OFF + r * 64 + ((c ^ swz(r)) << 4);
        uint32_t t[4];
        ldsm_x4(t, addr);
        fb[par][jp * 2][0] = t[0];      fb[par][jp * 2][1] = t[1];
        fb[par][jp * 2 + 1][0] = t[2];  fb[par][jp * 2 + 1][1] = t[3];
    };

    // ---- prologue: fill smem pipe; wait THEN sync; preload first fragments
    load_stage(0);
    load_stage(1);
    load_stage(2);
    CP_WAIT(1);                 // groups 0 and 1 complete (FIFO)
    __syncthreads();            // barrier AFTER wait -> cross-thread visible
#pragma unroll
    for (int jp = 0; jp < 4; ++jp) load_B_part(0, sbase, 0, jp);
    load_A(0, sbase, 0, 0);

    for (int s = 0; s < nStages; ++s) {
        const uint32_t sb  = sbase + (uint32_t)(s & (NSTAGE - 1)) * STAGE_BYTES;
        const uint32_t sbn = sbase + (uint32_t)((s + 1) & (NSTAGE - 1)) * STAGE_BYTES;
        const bool hasNext = (s + 1 < nStages);

        // kb = 0: compute fb[0]; prefetch fb[1] (this stage kb1), A frags
#pragma unroll
        for (int i = 0; i < 4; ++i) {
            const int cur = i & 1, nxt = cur ^ 1;
            if (i < 3) load_A(nxt, sb, 0, i + 1);
            else       load_A(nxt, sb, 1, 0);
            load_B_part(1, sb, 1, i);
#pragma unroll
            for (int j = 0; j < 8; ++j)
                mma16816(acc[i][j], fah[cur], fb[0][j]);
        }
        // kb = 1: compute fb[1]; prefetch fb[0] + A(0) for NEXT stage
#pragma unroll
        for (int i = 0; i < 4; ++i) {
            const int cur = i & 1, nxt = cur ^ 1;
            if (i < 3)        load_A(nxt, sb, 1, i + 1);
            else if (hasNext) load_A(nxt, sbn, 0, 0);
            if (hasNext)      load_B_part(0, sbn, 0, i);
#pragma unroll
            for (int j = 0; j < 8; ++j)
                mma16816(acc[i][j], fah[cur], fb[1][j]);
        }

        if (hasNext) {
            // issue next load, wait (per-thread), THEN barrier
            if (s + 3 < nStages) { load_stage(s + 3); CP_WAIT(1); }
            else                 { CP_WAIT(0); }
            __syncthreads();
        }
    }

    // ---- epilogue ----
    const int r0base = bm0 + wm * 64 + (lane >> 2);
    const int c0base = bn0 + wn * 64 + (lane & 3) * 2;

    float bz[8][2];
#pragma unroll
    for (int j = 0; j < 8; ++j) {
        const int c = c0base + j * 8;
        bz[j][0] = bias ? __ldg(bias + c)     : 0.0f;
        bz[j][1] = bias ? __ldg(bias + c + 1) : 0.0f;
    }

#pragma unroll
    for (int i = 0; i < 4; ++i) {
        const long long r0 = r0base + i * 16;
        const long long r1 = r0 + 8;
#pragma unroll
        for (int j = 0; j < 8; ++j) {
            const int c = c0base + j * 8;
            float v00 = acc[i][j][0] + bz[j][0];
            float v01 = acc[i][j][1] + bz[j][1];
            float v10 = acc[i][j][2] + bz[j][0];
            float v11 = acc[i][j][3] + bz[j][1];
            if (EPI == 0) {
                *(float2*)(Cf + cOff + r0 * N + c) = make_float2(v00, v01);
                *(float2*)(Cf + cOff + r1 * N + c) = make_float2(v10, v11);
            } else {
                *(__half2*)(Ch + cOff + r0 * N + c) =
                    __half2(__float2half_rn(v00), __float2half_rn(v01));
                *(__half2*)(Ch + cOff + r1 * N + c) =
                    __half2(__float2half_rn(v10), __float2half_rn(v11));
            }
        }
    }
}

template<int EPI>
__global__ void __launch_bounds__(128, 2)
gemm_mma(const __half* __restrict__ A, const __half* __restrict__ B,
         float* __restrict__ Cf, __half* __restrict__ Ch,
         const float* __restrict__ bias,
         int K, int N, long long sA, long long sB, long long sC)
{
    gemm_body<EPI>(A + blockIdx.z * sA, B + blockIdx.z * sB, Cf, Ch, bias,
                   K, N, blockIdx.y * 128, blockIdx.x * 128, blockIdx.z * sC);
}

// merged K+V projections: z=0 -> K, z=1 -> V (same A, K=CTX, N=DIM)
__global__ void __launch_bounds__(128, 2)
gemm_kv(const __half* __restrict__ Ac,
        const __half* __restrict__ Bk, const __half* __restrict__ Bv,
        __half* __restrict__ Ck, __half* __restrict__ Cv,
        const float* __restrict__ bk, const float* __restrict__ bv)
{
    const int z = blockIdx.z;
    gemm_body<2>(Ac, z ? Bv : Bk, nullptr, z ? Cv : Ck, z ? bv : bk,
                 CTX, DIM, blockIdx.y * 128, blockIdx.x * 128, 0);
}

// ---------------------------------------------------------------------------
// kernel_launch — gemmQ at launch index 3 (ncu profiles that slot).
// ---------------------------------------------------------------------------
extern "C" void kernel_launch(void* const* d_in, const int* in_sizes, int n_in,
                              void* d_out, int out_size)
{
    const float* x   = (const float*)d_in[0];
    const float* ctx = (const float*)d_in[1];
    const float* Wq  = (const float*)d_in[2];
    const float* bq  = (const float*)d_in[3];
    const float* Wk  = (const float*)d_in[4];
    const float* bk  = (const float*)d_in[5];
    const float* Wv  = (const float*)d_in[6];
    const float* bv  = (const float*)d_in[7];
    const float* Wo  = (const float*)d_in[8];
    const float* bo  = (const float*)d_in[9];
    float* out = (float*)d_out;

    __half *xh, *ch, *wqh, *wkh, *wvh, *woh;
    __half *qh, *kh, *vh, *vth, *oh, *ph;
    float* S;
    cudaGetSymbolAddress((void**)&xh, g_xh);
    cudaGetSymbolAddress((void**)&ch, g_ch);
    cudaGetSymbolAddress((void**)&wqh, g_wqh);
    cudaGetSymbolAddress((void**)&wkh, g_wkh);
    cudaGetSymbolAddress((void**)&wvh, g_wvh);
    cudaGetSymbolAddress((void**)&woh, g_woh);
    cudaGetSymbolAddress((void**)&qh, g_qh);
    cudaGetSymbolAddress((void**)&kh, g_kh);
    cudaGetSymbolAddress((void**)&vh, g_vh);
    cudaGetSymbolAddress((void**)&vth, g_vth);
    cudaGetSymbolAddress((void**)&oh, g_oh);
    cudaGetSymbolAddress((void**)&ph, g_ph);
    cudaGetSymbolAddress((void**)&S, g_s);

    cudaFuncSetAttribute(gemm_mma<0>, cudaFuncAttributeMaxDynamicSharedMemorySize, SMEM_TOTAL);
    cudaFuncSetAttribute(gemm_mma<2>, cudaFuncAttributeMaxDynamicSharedMemorySize, SMEM_TOTAL);
    cudaFuncSetAttribute(gemm_kv,     cudaFuncAttributeMaxDynamicSharedMemorySize, SMEM_TOTAL);

    dim3 grdP(DIM / 128, MROWS / 128, 1);
    dim3 blk(128);

    // idx 0-2: conversions feeding gemmQ
    conv_f32<<<(MROWS * (long long)DIM) / 2048, 256>>>(x, xh);
    conv_f32<<<(MROWS * (long long)CTX) / 2048, 256>>>(ctx, ch);
    conv_f32<<<(DIM * (long long)DIM) / 2048, 256>>>(Wq, wqh);
    // idx 3: Q projection  <-- ncu profiles this launch
    gemm_mma<2><<<grdP, blk, SMEM_TOTAL>>>(xh, wqh, nullptr, qh, bq,
                                           DIM, DIM, 0, 0, 0);
    // remaining conversions
    conv_f32<<<(DIM * (long long)CTX) / 2048, 256>>>(Wk, wkh);
    conv_f32<<<(DIM * (long long)CTX) / 2048, 256>>>(Wv, wvh);
    conv_f32<<<(DIM * (long long)DIM) / 2048, 256>>>(Wo, woh);
    // merged K + V projections (2048 CTAs -> ~99% wave efficiency)
    {
        dim3 grdKV(DIM / 128, MROWS / 128, 2);
        gemm_kv<<<grdKV, blk, SMEM_TOTAL>>>(ch, wkh, wvh, kh, vh, bk, bv);
    }

    // transpose V per batch -> [DIM, SEQ]
    transpose_v<<<dim3(DIM / 64, MROWS / 64, 1), 256>>>(vh, vth);

    // scores S = Q K^T (fp32)
    {
        dim3 grd(SEQ / 128, SEQ / 128, BATCH);
        gemm_mma<0><<<grd, blk, SMEM_TOTAL>>>(qh, kh, S, nullptr, nullptr,
                                              DIM, SEQ,
                                              (long long)SEQ * DIM, (long long)SEQ * DIM,
                                              (long long)SEQ * SEQ);
    }

    // softmax -> P (fp16)
    softmax_half<<<BATCH * SEQ, 256>>>(S, ph, 1.0f / sqrtf((float)DIM));

    // O = P V  -> fp16
    {
        dim3 grd(DIM / 128, SEQ / 128, BATCH);
        gemm_mma<2><<<grd, blk, SMEM_TOTAL>>>(ph, vth, nullptr, oh, nullptr,
                                              SEQ, DIM,
                                              (long long)SEQ * SEQ, (long long)DIM * SEQ,
                                              (long long)SEQ * DIM);
    }

    // out = O Wo^T + bo (fp32 -> d_out)
    gemm_mma<0><<<grdP, blk, SMEM_TOTAL>>>(oh, woh, out, nullptr, bo,
                                           DIM, DIM, 0, 0, 0);
}